// round 1
// baseline (speedup 1.0000x reference)
#include <cuda_runtime.h>

// LocalAttn fused kernel for GB300 (sm_103a).
// One block = one 16x16 spatial tile of one image. Halo = 18x18.
// Phase A: per input-group, stage x halo tile in SMEM, compute t=tanh(bn1(conv1)),
//          mn=bn2(conv2) -> mask (center, 72ch) and neighbor (halo, 8ch; depends
//          only on group 0). Then per-pixel softmax over 9 logits -> attn in SMEM.
// Phase B: per group, re-stage x halo tile (L2-resident second read), compute
//          v = wv@x over the halo, then out[g,c] = sum_k attn[g,k] * v[c, +dk].

#define NT 256

__global__ __launch_bounds__(256, 1)
void localattn_kernel(
    const float* __restrict__ x,
    const float* __restrict__ w1, const float* __restrict__ b1,
    const float* __restrict__ g1, const float* __restrict__ be1,
    const float* __restrict__ m1, const float* __restrict__ v1,
    const float* __restrict__ w2, const float* __restrict__ b2,
    const float* __restrict__ g2, const float* __restrict__ be2,
    const float* __restrict__ m2, const float* __restrict__ v2,
    const float* __restrict__ wv,
    float* __restrict__ out)
{
    extern __shared__ float sm[];
    float* s_w1   = sm;              // 2048   w1 (8,8,32)
    float* s_w2   = s_w1 + 2048;     // 640    w2 (8,10,8)
    float* s_wv   = s_w2 + 640;      // 1024   wv[g] staging (32,32)
    float* s_a1   = s_wv + 1024;     // 64     bn1 scale
    float* s_c1   = s_a1 + 64;       // 64     bn1 offset (bias folded)
    float* s_a2   = s_c1 + 64;       // 80     bn2 scale
    float* s_c2   = s_a2 + 80;       // 80     bn2 offset (bias folded)
    float* s_x    = s_c2 + 80;       // 324*36 x halo tile   [hp][ci] pitch 36
    float* s_v    = s_x + 11664;     // 324*36 v halo tile   [hp][ch] pitch 36
    float* s_mask = s_v + 11664;     // 256*73 mask then attn [px][72] pitch 73
    float* s_nb   = s_mask + 18688;  // 8*324  neighbor mn ch [g][hp]

    const int tid  = threadIdx.x;
    const int w0   = blockIdx.x * 16;
    const int h0   = blockIdx.y * 16;
    const int bimg = blockIdx.z;
    const float* xb = x + (size_t)bimg * 256 * 16384;

    // ---- load weights + fold BN params ----
    for (int i = tid; i < 2048; i += NT) s_w1[i] = w1[i];
    for (int i = tid; i < 640;  i += NT) s_w2[i] = w2[i];
    if (tid < 64) {
        float inv = g1[tid] * rsqrtf(v1[tid] + 1e-5f);
        s_a1[tid] = inv;
        s_c1[tid] = b1[tid] * inv + be1[tid] - m1[tid] * inv;
    } else if (tid >= 128 && tid < 208) {
        int c = tid - 128;
        float inv = g2[c] * rsqrtf(v2[c] + 1e-5f);
        s_a2[c] = inv;
        s_c2[c] = b2[c] * inv + be2[c] - m2[c] * inv;
    }
    __syncthreads();

    const int ty = tid >> 4, tx = tid & 15;
    const int hpc = (ty + 1) * 18 + (tx + 1);   // this thread's center halo-pixel

    // ================= Phase A: mask + neighbor + softmax =================
    for (int gi = 0; gi < 8; ++gi) {
        // stage x group gi halo tile (zero-fill outside image)
        for (int idx = tid; idx < 324 * 32; idx += NT) {
            int ci = idx / 324;
            int hp = idx - ci * 324;
            int hy = hp / 18, hx = hp - hy * 18;
            int h = h0 + hy - 1, w = w0 + hx - 1;
            float val = 0.f;
            if (((unsigned)h < 128u) & ((unsigned)w < 128u))
                val = xb[(gi * 32 + ci) * 16384 + h * 128 + w];
            s_x[hp * 36 + ci] = val;
        }
        __syncthreads();

        // center pixel: t group gi, then mn channels of group gi (mask part)
        {
            float t[8];
            #pragma unroll
            for (int o = 0; o < 8; o++) t[o] = 0.f;
            const float* wg = s_w1 + gi * 256;
            const float* xp = s_x + hpc * 36;
            #pragma unroll
            for (int ci = 0; ci < 32; ci += 4) {
                float4 xv = *(const float4*)(xp + ci);
                #pragma unroll
                for (int o = 0; o < 8; o++) {
                    float4 w4 = *(const float4*)(wg + o * 32 + ci);
                    t[o] += xv.x * w4.x + xv.y * w4.y + xv.z * w4.z + xv.w * w4.w;
                }
            }
            #pragma unroll
            for (int o = 0; o < 8; o++) {
                int ch = gi * 8 + o;
                t[o] = tanhf(t[o] * s_a1[ch] + s_c1[ch]);
            }
            const float* w2g = s_w2 + gi * 80;
            #pragma unroll
            for (int o2 = 0; o2 < 10; o2++) {
                int ch2 = gi * 10 + o2;
                if (ch2 >= 8) {   // mask channels only; ch2<8 (neighbor) handled on halo
                    float acc = 0.f;
                    #pragma unroll
                    for (int o = 0; o < 8; o++) acc += w2g[o2 * 8 + o] * t[o];
                    s_mask[tid * 73 + (ch2 - 8)] = acc * s_a2[ch2] + s_c2[ch2];
                }
            }
        }

        // halo pixels: neighbor channels (mn ch 0..7) — depend only on group 0
        if (gi == 0) {
            for (int hp = tid; hp < 324; hp += NT) {
                int hy = hp / 18, hx = hp - hy * 18;
                int h = h0 + hy - 1, w = w0 + hx - 1;
                bool inimg = ((unsigned)h < 128u) & ((unsigned)w < 128u);
                float t[8];
                #pragma unroll
                for (int o = 0; o < 8; o++) t[o] = 0.f;
                const float* xp = s_x + hp * 36;
                #pragma unroll
                for (int ci = 0; ci < 32; ci += 4) {
                    float4 xv = *(const float4*)(xp + ci);
                    #pragma unroll
                    for (int o = 0; o < 8; o++) {
                        float4 w4 = *(const float4*)(s_w1 + o * 32 + ci);
                        t[o] += xv.x * w4.x + xv.y * w4.y + xv.z * w4.z + xv.w * w4.w;
                    }
                }
                #pragma unroll
                for (int o = 0; o < 8; o++)
                    t[o] = tanhf(t[o] * s_a1[o] + s_c1[o]);
                #pragma unroll
                for (int o2 = 0; o2 < 8; o2++) {
                    float acc = 0.f;
                    #pragma unroll
                    for (int o = 0; o < 8; o++) acc += s_w2[o2 * 8 + o] * t[o];
                    float val = acc * s_a2[o2] + s_c2[o2];
                    s_nb[o2 * 324 + hp] = inimg ? val : 0.f;  // unfold zero-pads mn
                }
            }
        }
        __syncthreads();
    }

    // per-pixel softmax over the 9 logits of each group; attn overwrites mask
    for (int g = 0; g < 8; g++) {
        float l[9];
        #pragma unroll
        for (int k = 0; k < 9; k++) {
            int i = k / 3, j = k - i * 3;
            l[k] = s_mask[tid * 73 + g * 9 + k] + s_nb[g * 324 + (ty + i) * 18 + (tx + j)];
        }
        float mx = l[0];
        #pragma unroll
        for (int k = 1; k < 9; k++) mx = fmaxf(mx, l[k]);
        float sum = 0.f;
        #pragma unroll
        for (int k = 0; k < 9; k++) { l[k] = __expf(l[k] - mx); sum += l[k]; }
        float inv = 1.f / sum;
        #pragma unroll
        for (int k = 0; k < 9; k++) s_mask[tid * 73 + g * 9 + k] = l[k] * inv;
    }
    __syncthreads();

    // ================= Phase B: v-conv + attention combine =================
    for (int g = 0; g < 8; ++g) {
        // re-stage x group g halo (second read of x is L2-resident) + wv[g]
        for (int idx = tid; idx < 324 * 32; idx += NT) {
            int ci = idx / 324;
            int hp = idx - ci * 324;
            int hy = hp / 18, hx = hp - hy * 18;
            int h = h0 + hy - 1, w = w0 + hx - 1;
            float val = 0.f;
            if (((unsigned)h < 128u) & ((unsigned)w < 128u))
                val = xb[(g * 32 + ci) * 16384 + h * 128 + w];
            s_x[hp * 36 + ci] = val;
        }
        for (int i = tid; i < 1024; i += NT) s_wv[i] = wv[g * 1024 + i];
        __syncthreads();

        // v = wv[g] @ x[g] on the whole halo; zero outside image (unfold zero-pad)
        for (int item = tid; item < 4 * 324; item += NT) {
            int cb = item / 324;            // 8-channel chunk id
            int hp = item - cb * 324;
            int hy = hp / 18, hx = hp - hy * 18;
            int h = h0 + hy - 1, w = w0 + hx - 1;
            bool inimg = ((unsigned)h < 128u) & ((unsigned)w < 128u);
            float acc[8];
            #pragma unroll
            for (int o = 0; o < 8; o++) acc[o] = 0.f;
            if (inimg) {
                const float* xp = s_x + hp * 36;
                const float* wp = s_wv + cb * 256;
                #pragma unroll
                for (int ci = 0; ci < 32; ci += 4) {
                    float4 xv = *(const float4*)(xp + ci);
                    #pragma unroll
                    for (int o = 0; o < 8; o++) {
                        float4 w4 = *(const float4*)(wp + o * 32 + ci);
                        acc[o] += xv.x * w4.x + xv.y * w4.y + xv.z * w4.z + xv.w * w4.w;
                    }
                }
            }
            float* vp = s_v + hp * 36 + cb * 8;
            #pragma unroll
            for (int o = 0; o < 8; o++) vp[o] = acc[o];
        }
        __syncthreads();

        // combine: out[g,c] = sum_k attn[g,k] * v[c] at neighbor k
        {
            float a[9];
            #pragma unroll
            for (int k = 0; k < 9; k++) a[k] = s_mask[tid * 73 + g * 9 + k];
            float* ob = out + ((size_t)(bimg * 256 + g * 32)) * 16384
                            + (h0 + ty) * 128 + (w0 + tx);
            #pragma unroll
            for (int c = 0; c < 32; c += 4) {
                float ax = 0.f, ay = 0.f, az = 0.f, aw = 0.f;
                #pragma unroll
                for (int k = 0; k < 9; k++) {
                    int i = k / 3, j = k - i * 3;
                    const float4 vv = *(const float4*)(s_v + ((ty + i) * 18 + (tx + j)) * 36 + c);
                    ax += a[k] * vv.x; ay += a[k] * vv.y;
                    az += a[k] * vv.z; aw += a[k] * vv.w;
                }
                ob[(c + 0) * 16384] = ax;
                ob[(c + 1) * 16384] = ay;
                ob[(c + 2) * 16384] = az;
                ob[(c + 3) * 16384] = aw;
            }
        }
        __syncthreads();
    }
}

static const int SMEM_BYTES = (2048 + 640 + 1024 + 64 + 64 + 80 + 80
                               + 11664 + 11664 + 18688 + 2592) * 4;  // 194432

extern "C" void kernel_launch(void* const* d_in, const int* in_sizes, int n_in,
                              void* d_out, int out_size) {
    const float* x   = (const float*)d_in[0];
    const float* w1  = (const float*)d_in[1];
    const float* b1  = (const float*)d_in[2];
    const float* g1  = (const float*)d_in[3];
    const float* be1 = (const float*)d_in[4];
    const float* m1  = (const float*)d_in[5];
    const float* v1  = (const float*)d_in[6];
    const float* w2  = (const float*)d_in[7];
    const float* b2  = (const float*)d_in[8];
    const float* g2  = (const float*)d_in[9];
    const float* be2 = (const float*)d_in[10];
    const float* m2  = (const float*)d_in[11];
    const float* v2  = (const float*)d_in[12];
    const float* wv  = (const float*)d_in[13];
    float* out = (float*)d_out;

    cudaFuncSetAttribute(localattn_kernel,
                         cudaFuncAttributeMaxDynamicSharedMemorySize, SMEM_BYTES);
    dim3 grid(8, 8, 2);
    localattn_kernel<<<grid, 256, SMEM_BYTES>>>(
        x, w1, b1, g1, be1, m1, v1, w2, b2, g2, be2, m2, v2, wv, out);
}

// round 2
// speedup vs baseline: 1.7099x; 1.7099x over previous
#include <cuda_runtime.h>

// LocalAttn, 2-kernel pipeline for GB300 (sm_103a).
// Kernel A: per (256-px chunk, group): compute mn = bn2(conv2(tanh(bn1(conv1(x)))))
//           into g_mn scratch, and write pixel-major transpose g_xt of x.
// Kernel M: per (16x16 tile, group): softmax(mask + unfold(neighbor)) in registers,
//           v = wv @ x on 18x18 halo in smem, combine, write out.

typedef unsigned long long ull;

__device__ float g_xt[2u * 16384u * 256u];   // [img][px][ch]  33.5 MB
__device__ float g_mn[2u * 80u * 16384u];    // [img][ch][px]  10.5 MB

__device__ __forceinline__ ull fma2(ull a, ull b, ull c) {
    ull d;
    asm("fma.rn.f32x2 %0, %1, %2, %3;" : "=l"(d) : "l"(a), "l"(b), "l"(c));
    return d;
}
__device__ __forceinline__ float hadd2(ull a) {
    float x, y;
    asm("mov.b64 {%0,%1}, %2;" : "=f"(x), "=f"(y) : "l"(a));
    return x + y;
}
__device__ __forceinline__ ull pk2(float lo, float hi) {
    ull r;
    asm("mov.b64 %0, {%1,%2};" : "=l"(r) : "f"(lo), "f"(hi));
    return r;
}

// ============================ Kernel A ============================
// grid (64, 8, 2) = (px chunk, group, img), block 256.
__global__ __launch_bounds__(256)
void mn_xt_kernel(
    const float* __restrict__ x,
    const float* __restrict__ w1, const float* __restrict__ b1,
    const float* __restrict__ g1, const float* __restrict__ be1,
    const float* __restrict__ m1, const float* __restrict__ v1,
    const float* __restrict__ w2, const float* __restrict__ b2,
    const float* __restrict__ g2, const float* __restrict__ be2,
    const float* __restrict__ m2, const float* __restrict__ v2)
{
    __shared__ __align__(16) float s_px[256 * 34];   // [px][ci] pitch 34 (conflict-free)
    __shared__ __align__(16) float s_w1g[256];
    __shared__ __align__(16) float s_w2g[80];
    __shared__ float s_a1[8], s_c1[8], s_a2[10], s_c2[10];

    const int t    = threadIdx.x;
    const int lane = t & 31;
    const int wq   = t >> 5;
    const int px0  = blockIdx.x * 256;
    const int g    = blockIdx.y;
    const int img  = blockIdx.z;

    // weights + folded BN params
    s_w1g[t] = w1[g * 256 + t];
    if (t < 80) s_w2g[t] = w2[g * 80 + t];
    if (t < 8) {
        int ch = g * 8 + t;
        float inv = g1[ch] * rsqrtf(v1[ch] + 1e-5f);
        s_a1[t] = inv;
        s_c1[t] = b1[ch] * inv + be1[ch] - m1[ch] * inv;
    } else if (t >= 32 && t < 42) {
        int o = t - 32, ch = g * 10 + o;
        float inv = g2[ch] * rsqrtf(v2[ch] + 1e-5f);
        s_a2[o] = inv;
        s_c2[o] = b2[ch] * inv + be2[ch] - m2[ch] * inv;
    }

    // stage x slice (lane = channel) + write pixel-major transpose g_xt
    const float* xb = x + ((size_t)img * 256 + g * 32 + lane) * 16384 + px0;
    float* xtb = g_xt + ((size_t)img * 16384 + px0) * 256 + g * 32 + lane;
    #pragma unroll
    for (int it = 0; it < 8; ++it) {
        int p4 = (wq + it * 8) * 4;
        float4 v4 = *(const float4*)(xb + p4);
        s_px[(p4 + 0) * 34 + lane] = v4.x;
        s_px[(p4 + 1) * 34 + lane] = v4.y;
        s_px[(p4 + 2) * 34 + lane] = v4.z;
        s_px[(p4 + 3) * 34 + lane] = v4.w;
        xtb[(size_t)(p4 + 0) * 256] = v4.x;
        xtb[(size_t)(p4 + 1) * 256] = v4.y;
        xtb[(size_t)(p4 + 2) * 256] = v4.z;
        xtb[(size_t)(p4 + 3) * 256] = v4.w;
    }
    __syncthreads();

    // conv1 (packed f32x2) -> bn -> tanh -> conv2 -> bn -> g_mn
    const float* xp = s_px + t * 34;
    ull acc[8];
    #pragma unroll
    for (int o = 0; o < 8; o++) acc[o] = 0ULL;
    #pragma unroll
    for (int c2 = 0; c2 < 16; c2++) {
        ull xv = *(const ull*)(xp + c2 * 2);
        #pragma unroll
        for (int o = 0; o < 8; o++)
            acc[o] = fma2(xv, *(const ull*)(s_w1g + o * 32 + c2 * 2), acc[o]);
    }
    float tv[8];
    #pragma unroll
    for (int o = 0; o < 8; o++)
        tv[o] = tanhf(hadd2(acc[o]) * s_a1[o] + s_c1[o]);

    float* mb = g_mn + ((size_t)img * 80 + g * 10) * 16384 + px0 + t;
    #pragma unroll
    for (int o2 = 0; o2 < 10; o2++) {
        float a = 0.f;
        #pragma unroll
        for (int o = 0; o < 8; o++) a += tv[o] * s_w2g[o2 * 8 + o];
        mb[(size_t)o2 * 16384] = a * s_a2[o2] + s_c2[o2];
    }
}

// ============================ Kernel M ============================
// grid (8, 8, 16): z = img*8 + g. block 256 (one thread per center pixel).
// smem: s_x 11664 | s_v 11664 | s_wv 1056 | s_nb 324  -> 24708 floats (98.8 KB)
__global__ __launch_bounds__(256, 2)
void attn_kernel(const float* __restrict__ wv, float* __restrict__ out)
{
    extern __shared__ __align__(16) float sm[];
    float* s_x  = sm;                 // [hp][ci] pitch 36
    float* s_v  = sm + 11664;         // [hp][co] pitch 36
    float* s_wv = sm + 23328;         // [cb][o][ci] cb pitch 264
    float* s_nb = sm + 24384;         // [hp]

    const int t   = threadIdx.x;
    const int ty  = t >> 4, tx = t & 15;
    const int w0  = blockIdx.x * 16;
    const int h0  = blockIdx.y * 16;
    const int img = blockIdx.z >> 3;
    const int g   = blockIdx.z & 7;

    // wv[g] into padded smem layout
    for (int i = t; i < 1024; i += 256)
        s_wv[(i >> 8) * 264 + (i & 255)] = wv[g * 1024 + i];

    // neighbor channel g on 18x18 halo (zero outside image)
    const float* nbg = g_mn + ((size_t)img * 80 + g) * 16384;
    for (int hp = t; hp < 324; hp += 256) {
        int hy = hp / 18, hx = hp - hy * 18;
        int h = h0 + hy - 1, w = w0 + hx - 1;
        float v = 0.f;
        if (((unsigned)h < 128u) & ((unsigned)w < 128u)) v = nbg[h * 128 + w];
        s_nb[hp] = v;
    }

    // mask channels for this group's center pixel -> registers
    const int px = (h0 + ty) * 128 + (w0 + tx);
    float m[9];
    {
        const float* mbase = g_mn + ((size_t)img * 80 + 8 + g * 9) * 16384 + px;
        #pragma unroll
        for (int k = 0; k < 9; k++) m[k] = mbase[(size_t)k * 16384];
    }

    // stage x halo from pixel-major g_xt (coalesced float4)
    {
        const float* xt = g_xt + (size_t)img * 16384 * 256 + g * 32;
        for (int idx = t; idx < 2592; idx += 256) {
            int hp = idx >> 3, q = idx & 7;
            int hy = hp / 18, hx = hp - hy * 18;
            int h = h0 + hy - 1, w = w0 + hx - 1;
            float4 v4 = make_float4(0.f, 0.f, 0.f, 0.f);
            if (((unsigned)h < 128u) & ((unsigned)w < 128u))
                v4 = *(const float4*)(xt + (size_t)(h * 128 + w) * 256 + q * 4);
            *(float4*)(s_x + hp * 36 + q * 4) = v4;
        }
    }
    __syncthreads();

    // softmax over 9 logits (all in registers)
    float a[9];
    {
        #pragma unroll
        for (int k = 0; k < 9; k++) {
            int i = k / 3, j = k - i * 3;
            a[k] = m[k] + s_nb[(ty + i) * 18 + (tx + j)];
        }
        float mx = a[0];
        #pragma unroll
        for (int k = 1; k < 9; k++) mx = fmaxf(mx, a[k]);
        float s = 0.f;
        #pragma unroll
        for (int k = 0; k < 9; k++) { a[k] = __expf(a[k] - mx); s += a[k]; }
        float inv = 1.f / s;
        #pragma unroll
        for (int k = 0; k < 9; k++) a[k] *= inv;
    }

    // v-conv on halo: item = (hp pair, 8-channel chunk), packed f32x2
    for (int item = t; item < 648; item += 256) {
        int hp2 = item >> 2, cb = item & 3;
        const float* xA = s_x + hp2 * 72;
        const float* xB = xA + 36;
        const float* wp = s_wv + cb * 264;
        ull acc[16];
        #pragma unroll
        for (int o = 0; o < 16; o++) acc[o] = 0ULL;
        #pragma unroll
        for (int c2 = 0; c2 < 16; c2++) {
            ull xa = *(const ull*)(xA + c2 * 2);
            ull xb2 = *(const ull*)(xB + c2 * 2);
            #pragma unroll
            for (int o = 0; o < 8; o++) {
                ull wv2 = *(const ull*)(wp + o * 32 + c2 * 2);
                acc[o]     = fma2(xa,  wv2, acc[o]);
                acc[8 + o] = fma2(xb2, wv2, acc[8 + o]);
            }
        }
        float4 r;
        r.x = hadd2(acc[0]); r.y = hadd2(acc[1]); r.z = hadd2(acc[2]); r.w = hadd2(acc[3]);
        *(float4*)(s_v + hp2 * 72 + cb * 8) = r;
        r.x = hadd2(acc[4]); r.y = hadd2(acc[5]); r.z = hadd2(acc[6]); r.w = hadd2(acc[7]);
        *(float4*)(s_v + hp2 * 72 + cb * 8 + 4) = r;
        r.x = hadd2(acc[8]); r.y = hadd2(acc[9]); r.z = hadd2(acc[10]); r.w = hadd2(acc[11]);
        *(float4*)(s_v + hp2 * 72 + 36 + cb * 8) = r;
        r.x = hadd2(acc[12]); r.y = hadd2(acc[13]); r.z = hadd2(acc[14]); r.w = hadd2(acc[15]);
        *(float4*)(s_v + hp2 * 72 + 36 + cb * 8 + 4) = r;
    }
    __syncthreads();

    // combine: out[c] = sum_k a[k] * v[c] at neighbor k
    {
        int hpk[9];
        #pragma unroll
        for (int k = 0; k < 9; k++) {
            int i = k / 3, j = k - i * 3;
            hpk[k] = ((ty + i) * 18 + (tx + j)) * 36;
        }
        float* ob = out + ((size_t)img * 256 + g * 32) * 16384 + px;
        #pragma unroll
        for (int c4 = 0; c4 < 8; c4++) {
            float ax = 0.f, ay = 0.f, az = 0.f, aw = 0.f;
            #pragma unroll
            for (int k = 0; k < 9; k++) {
                float4 vv = *(const float4*)(s_v + hpk[k] + c4 * 4);
                ax += a[k] * vv.x; ay += a[k] * vv.y;
                az += a[k] * vv.z; aw += a[k] * vv.w;
            }
            ob[(size_t)(c4 * 4 + 0) * 16384] = ax;
            ob[(size_t)(c4 * 4 + 1) * 16384] = ay;
            ob[(size_t)(c4 * 4 + 2) * 16384] = az;
            ob[(size_t)(c4 * 4 + 3) * 16384] = aw;
        }
    }
}

static const int M_SMEM = 24708 * 4;   // 98832 B

extern "C" void kernel_launch(void* const* d_in, const int* in_sizes, int n_in,
                              void* d_out, int out_size) {
    const float* x   = (const float*)d_in[0];
    const float* w1  = (const float*)d_in[1];
    const float* b1  = (const float*)d_in[2];
    const float* g1  = (const float*)d_in[3];
    const float* be1 = (const float*)d_in[4];
    const float* m1  = (const float*)d_in[5];
    const float* v1  = (const float*)d_in[6];
    const float* w2  = (const float*)d_in[7];
    const float* b2  = (const float*)d_in[8];
    const float* g2  = (const float*)d_in[9];
    const float* be2 = (const float*)d_in[10];
    const float* m2  = (const float*)d_in[11];
    const float* v2  = (const float*)d_in[12];
    const float* wv  = (const float*)d_in[13];
    float* out = (float*)d_out;

    static int inited = 0;
    if (!inited) {
        cudaFuncSetAttribute(attn_kernel,
                             cudaFuncAttributeMaxDynamicSharedMemorySize, M_SMEM);
        inited = 1;
    }

    mn_xt_kernel<<<dim3(64, 8, 2), 256>>>(x, w1, b1, g1, be1, m1, v1,
                                          w2, b2, g2, be2, m2, v2);
    attn_kernel<<<dim3(8, 8, 16), 256, M_SMEM>>>(wv, out);
}

// round 3
// speedup vs baseline: 1.8987x; 1.1104x over previous
#include <cuda_runtime.h>

// LocalAttn, 2-kernel pipeline for GB300 (sm_103a), round 3.
// Kernel A (stage1): per (256-px chunk, group, img):
//   stage x[32ci] per px in smem, compute:
//     mn = bn2(conv2(tanh(bn1(conv1 x))))  -> g_mn  (channel-major)
//     v  = wv @ x                          -> g_v   (pixel-major)
// Kernel M (combine): per (16x16 tile, group, img):
//   softmax(mask + unfold(neighbor)) in regs, gather v halo from g_v,
//   out = attn . unfold(v).

typedef unsigned long long ull;

__device__ float g_v [2u * 16384u * 256u];   // [img][px][ch]  33.5 MB
__device__ float g_mn[2u * 80u * 16384u];    // [img][ch][px]  10.5 MB

__device__ __forceinline__ ull fma2(ull a, ull b, ull c) {
    ull d;
    asm("fma.rn.f32x2 %0, %1, %2, %3;" : "=l"(d) : "l"(a), "l"(b), "l"(c));
    return d;
}
__device__ __forceinline__ float hadd2(ull a) {
    float x, y;
    asm("mov.b64 {%0,%1}, %2;" : "=f"(x), "=f"(y) : "l"(a));
    return x + y;
}

// ============================ Kernel A ============================
// grid (64, 8, 2) = (px chunk, group, img), block 256, one thread per pixel.
__global__ __launch_bounds__(256, 3)
void stage1_kernel(
    const float* __restrict__ x,
    const float* __restrict__ w1, const float* __restrict__ b1,
    const float* __restrict__ g1, const float* __restrict__ be1,
    const float* __restrict__ m1, const float* __restrict__ v1,
    const float* __restrict__ w2, const float* __restrict__ b2,
    const float* __restrict__ g2, const float* __restrict__ be2,
    const float* __restrict__ m2, const float* __restrict__ v2,
    const float* __restrict__ wv)
{
    __shared__ __align__(16) float s_px[256 * 36];   // [px][ci] pitch 36 (16B aligned)
    __shared__ __align__(16) float s_w1g[256];       // w1[g]  (8,32)
    __shared__ __align__(16) float s_wvg[1024];      // wv[g]  (32,32)
    __shared__ __align__(16) float s_w2g[80];        // w2[g]  (10,8)
    __shared__ float s_a1[8], s_c1[8], s_a2[10], s_c2[10];

    const int t    = threadIdx.x;
    const int lane = t & 31;
    const int wq   = t >> 5;
    const int px0  = blockIdx.x * 256;
    const int g    = blockIdx.y;
    const int img  = blockIdx.z;

    // weights + folded BN params
    s_w1g[t] = w1[g * 256 + t];
    for (int i = t; i < 1024; i += 256) s_wvg[i] = wv[g * 1024 + i];
    if (t < 80) s_w2g[t] = w2[g * 80 + t];
    if (t < 8) {
        int ch = g * 8 + t;
        float inv = g1[ch] * rsqrtf(v1[ch] + 1e-5f);
        s_a1[t] = inv;
        s_c1[t] = b1[ch] * inv + be1[ch] - m1[ch] * inv;
    } else if (t >= 32 && t < 42) {
        int o = t - 32, ch = g * 10 + o;
        float inv = g2[ch] * rsqrtf(v2[ch] + 1e-5f);
        s_a2[o] = inv;
        s_c2[o] = b2[ch] * inv + be2[ch] - m2[ch] * inv;
    }

    // stage x slice (lane = channel)
    const float* xb = x + ((size_t)img * 256 + g * 32 + lane) * 16384 + px0;
    #pragma unroll
    for (int it = 0; it < 8; ++it) {
        int p4 = (wq + it * 8) * 4;
        float4 v4 = *(const float4*)(xb + p4);
        s_px[(p4 + 0) * 36 + lane] = v4.x;
        s_px[(p4 + 1) * 36 + lane] = v4.y;
        s_px[(p4 + 2) * 36 + lane] = v4.z;
        s_px[(p4 + 3) * 36 + lane] = v4.w;
    }
    __syncthreads();

    const float* xp = s_px + t * 36;

    // ---- conv1 -> bn -> tanh -> conv2 -> bn -> g_mn ----
    {
        ull acc[8];
        #pragma unroll
        for (int o = 0; o < 8; o++) acc[o] = 0ULL;
        #pragma unroll
        for (int c4 = 0; c4 < 8; c4++) {
            ulonglong2 xv = *(const ulonglong2*)(xp + c4 * 4);
            #pragma unroll
            for (int o = 0; o < 8; o++) {
                ulonglong2 wp = *(const ulonglong2*)(s_w1g + o * 32 + c4 * 4);
                acc[o] = fma2(xv.x, wp.x, acc[o]);
                acc[o] = fma2(xv.y, wp.y, acc[o]);
            }
        }
        float tv[8];
        #pragma unroll
        for (int o = 0; o < 8; o++)
            tv[o] = tanhf(hadd2(acc[o]) * s_a1[o] + s_c1[o]);

        float* mb = g_mn + ((size_t)img * 80 + g * 10) * 16384 + px0 + t;
        #pragma unroll
        for (int o2 = 0; o2 < 10; o2++) {
            float a = 0.f;
            #pragma unroll
            for (int o = 0; o < 8; o++) a += tv[o] * s_w2g[o2 * 8 + o];
            mb[(size_t)o2 * 16384] = a * s_a2[o2] + s_c2[o2];
        }
    }

    // ---- v = wv @ x  -> g_v pixel-major (two halves of 16 outputs) ----
    float* vb = g_v + ((size_t)img * 16384 + px0 + t) * 256 + g * 32;
    #pragma unroll
    for (int half = 0; half < 2; half++) {
        ull vacc[16];
        #pragma unroll
        for (int o = 0; o < 16; o++) vacc[o] = 0ULL;
        #pragma unroll
        for (int c4 = 0; c4 < 8; c4++) {
            ulonglong2 xv = *(const ulonglong2*)(xp + c4 * 4);
            #pragma unroll
            for (int o = 0; o < 16; o++) {
                ulonglong2 wp = *(const ulonglong2*)(s_wvg + (half * 16 + o) * 32 + c4 * 4);
                vacc[o] = fma2(xv.x, wp.x, vacc[o]);
                vacc[o] = fma2(xv.y, wp.y, vacc[o]);
            }
        }
        #pragma unroll
        for (int j = 0; j < 4; j++) {
            float4 r;
            r.x = hadd2(vacc[j * 4 + 0]);
            r.y = hadd2(vacc[j * 4 + 1]);
            r.z = hadd2(vacc[j * 4 + 2]);
            r.w = hadd2(vacc[j * 4 + 3]);
            *(float4*)(vb + half * 16 + j * 4) = r;
        }
    }
}

// ============================ Kernel M ============================
// grid (8, 8, 16): z = img*8 + g. block 256 (one thread per center pixel).
__global__ __launch_bounds__(256, 4)
void combine_kernel(float* __restrict__ out)
{
    __shared__ __align__(16) float s_v[324 * 36];   // [hp][co] pitch 36
    __shared__ float s_nb[324];

    const int t   = threadIdx.x;
    const int ty  = t >> 4, tx = t & 15;
    const int w0  = blockIdx.x * 16;
    const int h0  = blockIdx.y * 16;
    const int img = blockIdx.z >> 3;
    const int g   = blockIdx.z & 7;

    // neighbor channel g on 18x18 halo (zero outside image)
    const float* nbg = g_mn + ((size_t)img * 80 + g) * 16384;
    for (int hp = t; hp < 324; hp += 256) {
        int hy = hp / 18, hx = hp - hy * 18;
        int h = h0 + hy - 1, w = w0 + hx - 1;
        float v = 0.f;
        if (((unsigned)h < 128u) & ((unsigned)w < 128u)) v = nbg[h * 128 + w];
        s_nb[hp] = v;
    }

    // mask channels for this group's center pixel -> registers
    const int px = (h0 + ty) * 128 + (w0 + tx);
    float m[9];
    {
        const float* mbase = g_mn + ((size_t)img * 80 + 8 + g * 9) * 16384 + px;
        #pragma unroll
        for (int k = 0; k < 9; k++) m[k] = mbase[(size_t)k * 16384];
    }

    // stage v halo from pixel-major g_v (coalesced float4)
    {
        const float* vt = g_v + (size_t)img * 16384 * 256 + g * 32;
        for (int idx = t; idx < 2592; idx += 256) {
            int hp = idx >> 3, q = idx & 7;
            int hy = hp / 18, hx = hp - hy * 18;
            int h = h0 + hy - 1, w = w0 + hx - 1;
            float4 v4 = make_float4(0.f, 0.f, 0.f, 0.f);
            if (((unsigned)h < 128u) & ((unsigned)w < 128u))
                v4 = *(const float4*)(vt + (size_t)(h * 128 + w) * 256 + q * 4);
            *(float4*)(s_v + hp * 36 + q * 4) = v4;
        }
    }
    __syncthreads();

    // softmax over 9 logits (registers)
    float a[9];
    {
        #pragma unroll
        for (int k = 0; k < 9; k++) {
            int i = k / 3, j = k - i * 3;
            a[k] = m[k] + s_nb[(ty + i) * 18 + (tx + j)];
        }
        float mx = a[0];
        #pragma unroll
        for (int k = 1; k < 9; k++) mx = fmaxf(mx, a[k]);
        float s = 0.f;
        #pragma unroll
        for (int k = 0; k < 9; k++) { a[k] = __expf(a[k] - mx); s += a[k]; }
        float inv = 1.f / s;
        #pragma unroll
        for (int k = 0; k < 9; k++) a[k] *= inv;
    }

    // combine: out[c] = sum_k a[k] * v[c] at neighbor k
    {
        int hpk[9];
        #pragma unroll
        for (int k = 0; k < 9; k++) {
            int i = k / 3, j = k - i * 3;
            hpk[k] = ((ty + i) * 18 + (tx + j)) * 36;
        }
        float* ob = out + ((size_t)img * 256 + g * 32) * 16384 + px;
        #pragma unroll
        for (int c4 = 0; c4 < 8; c4++) {
            float ax = 0.f, ay = 0.f, az = 0.f, aw = 0.f;
            #pragma unroll
            for (int k = 0; k < 9; k++) {
                float4 vv = *(const float4*)(s_v + hpk[k] + c4 * 4);
                ax += a[k] * vv.x; ay += a[k] * vv.y;
                az += a[k] * vv.z; aw += a[k] * vv.w;
            }
            ob[(size_t)(c4 * 4 + 0) * 16384] = ax;
            ob[(size_t)(c4 * 4 + 1) * 16384] = ay;
            ob[(size_t)(c4 * 4 + 2) * 16384] = az;
            ob[(size_t)(c4 * 4 + 3) * 16384] = aw;
        }
    }
}

extern "C" void kernel_launch(void* const* d_in, const int* in_sizes, int n_in,
                              void* d_out, int out_size) {
    const float* x   = (const float*)d_in[0];
    const float* w1  = (const float*)d_in[1];
    const float* b1  = (const float*)d_in[2];
    const float* g1  = (const float*)d_in[3];
    const float* be1 = (const float*)d_in[4];
    const float* m1  = (const float*)d_in[5];
    const float* v1  = (const float*)d_in[6];
    const float* w2  = (const float*)d_in[7];
    const float* b2  = (const float*)d_in[8];
    const float* g2  = (const float*)d_in[9];
    const float* be2 = (const float*)d_in[10];
    const float* m2  = (const float*)d_in[11];
    const float* v2  = (const float*)d_in[12];
    const float* wv  = (const float*)d_in[13];
    float* out = (float*)d_out;

    stage1_kernel<<<dim3(64, 8, 2), 256>>>(x, w1, b1, g1, be1, m1, v1,
                                           w2, b2, g2, be2, m2, v2, wv);
    combine_kernel<<<dim3(8, 8, 16), 256>>>(out);
}

// round 4
// speedup vs baseline: 2.2412x; 1.1804x over previous
#include <cuda_runtime.h>

// LocalAttn, 2-kernel pipeline for GB300 (sm_103a), round 4.
// Kernel A (stage1): per (256-px chunk, group, img):
//   stage x[32ci] per px in smem -> registers, compute:
//     mn = bn2(conv2(tanh(bn1(conv1 x))))  -> g_mn [img][ch][px]
//     v  = wv @ x -> own smem row -> coalesced -> g_v [img][g][px][32]
// Kernel M (combine): per (16x16 tile, group, img):
//   gather v halo (coalesced, L2), softmax(mask + nb) in regs, combine.

typedef unsigned long long ull;

__device__ float g_v [2u * 8u * 16384u * 32u];   // [img][g][px][32]  33.5 MB
__device__ float g_mn[2u * 80u * 16384u];        // [img][ch][px]     10.5 MB

__device__ __forceinline__ ull fma2(ull a, ull b, ull c) {
    ull d;
    asm("fma.rn.f32x2 %0, %1, %2, %3;" : "=l"(d) : "l"(a), "l"(b), "l"(c));
    return d;
}
__device__ __forceinline__ float hadd2(ull a) {
    float x, y;
    asm("mov.b64 {%0,%1}, %2;" : "=f"(x), "=f"(y) : "l"(a));
    return x + y;
}

// ============================ Kernel A ============================
// grid (64, 8, 2) = (px chunk, group, img), block 256, one thread per pixel.
__global__ __launch_bounds__(256, 3)
void stage1_kernel(
    const float* __restrict__ x,
    const float* __restrict__ w1, const float* __restrict__ b1,
    const float* __restrict__ g1, const float* __restrict__ be1,
    const float* __restrict__ m1, const float* __restrict__ v1,
    const float* __restrict__ w2, const float* __restrict__ b2,
    const float* __restrict__ g2, const float* __restrict__ be2,
    const float* __restrict__ m2, const float* __restrict__ v2,
    const float* __restrict__ wv)
{
    __shared__ __align__(16) float s_px[256 * 36];   // [px][ci] pitch 36; later v
    __shared__ __align__(16) float s_w1g[256];       // w1[g]  (8,32)
    __shared__ __align__(16) float s_wvg[1024];      // wv[g]  (32,32)
    __shared__ __align__(16) float s_w2g[80];        // w2[g]  (10,8)
    __shared__ float s_a1[8], s_c1[8], s_a2[10], s_c2[10];

    const int t    = threadIdx.x;
    const int lane = t & 31;
    const int wq   = t >> 5;
    const int px0  = blockIdx.x * 256;
    const int g    = blockIdx.y;
    const int img  = blockIdx.z;

    // weights + folded BN params
    s_w1g[t] = w1[g * 256 + t];
    for (int i = t; i < 1024; i += 256) s_wvg[i] = wv[g * 1024 + i];
    if (t < 80) s_w2g[t] = w2[g * 80 + t];
    if (t < 8) {
        int ch = g * 8 + t;
        float inv = g1[ch] * rsqrtf(v1[ch] + 1e-5f);
        s_a1[t] = inv;
        s_c1[t] = b1[ch] * inv + be1[ch] - m1[ch] * inv;
    } else if (t >= 32 && t < 42) {
        int o = t - 32, ch = g * 10 + o;
        float inv = g2[ch] * rsqrtf(v2[ch] + 1e-5f);
        s_a2[o] = inv;
        s_c2[o] = b2[ch] * inv + be2[ch] - m2[ch] * inv;
    }

    // stage x slice (lane = channel), transpose via smem
    const float* xb = x + ((size_t)img * 256 + g * 32 + lane) * 16384 + px0;
    #pragma unroll
    for (int it = 0; it < 8; ++it) {
        int p4 = (wq + it * 8) * 4;
        float4 v4 = *(const float4*)(xb + p4);
        s_px[(p4 + 0) * 36 + lane] = v4.x;
        s_px[(p4 + 1) * 36 + lane] = v4.y;
        s_px[(p4 + 2) * 36 + lane] = v4.z;
        s_px[(p4 + 3) * 36 + lane] = v4.w;
    }
    __syncthreads();

    // pull own x row (32 floats) into registers; row t is thread-private
    float* xrow = s_px + t * 36;
    ulonglong2 xr[8];
    #pragma unroll
    for (int c4 = 0; c4 < 8; c4++)
        xr[c4] = *(const ulonglong2*)(xrow + c4 * 4);

    // ---- conv1 -> bn -> tanh -> conv2 -> bn -> g_mn ----
    {
        ull acc[8];
        #pragma unroll
        for (int o = 0; o < 8; o++) acc[o] = 0ULL;
        #pragma unroll
        for (int c4 = 0; c4 < 8; c4++) {
            #pragma unroll
            for (int o = 0; o < 8; o++) {
                ulonglong2 wp = *(const ulonglong2*)(s_w1g + o * 32 + c4 * 4);
                acc[o] = fma2(xr[c4].x, wp.x, acc[o]);
                acc[o] = fma2(xr[c4].y, wp.y, acc[o]);
            }
        }
        float tv[8];
        #pragma unroll
        for (int o = 0; o < 8; o++)
            tv[o] = tanhf(hadd2(acc[o]) * s_a1[o] + s_c1[o]);

        float* mb = g_mn + ((size_t)img * 80 + g * 10) * 16384 + px0 + t;
        #pragma unroll
        for (int o2 = 0; o2 < 10; o2++) {
            float a = 0.f;
            #pragma unroll
            for (int o = 0; o < 8; o++) a += tv[o] * s_w2g[o2 * 8 + o];
            mb[(size_t)o2 * 16384] = a * s_a2[o2] + s_c2[o2];
        }
    }

    // ---- v = wv @ x in 4 chunks of 8 outputs; write into own row ----
    #pragma unroll
    for (int ch = 0; ch < 4; ch++) {
        ull acc[8];
        #pragma unroll
        for (int o = 0; o < 8; o++) acc[o] = 0ULL;
        #pragma unroll
        for (int c4 = 0; c4 < 8; c4++) {
            #pragma unroll
            for (int o = 0; o < 8; o++) {
                ulonglong2 wp = *(const ulonglong2*)(s_wvg + (ch * 8 + o) * 32 + c4 * 4);
                acc[o] = fma2(xr[c4].x, wp.x, acc[o]);
                acc[o] = fma2(xr[c4].y, wp.y, acc[o]);
            }
        }
        float4 r;
        r.x = hadd2(acc[0]); r.y = hadd2(acc[1]);
        r.z = hadd2(acc[2]); r.w = hadd2(acc[3]);
        *(float4*)(xrow + ch * 8) = r;
        r.x = hadd2(acc[4]); r.y = hadd2(acc[5]);
        r.z = hadd2(acc[6]); r.w = hadd2(acc[7]);
        *(float4*)(xrow + ch * 8 + 4) = r;
    }
    __syncthreads();

    // ---- coalesced store of v: warp writes 512B contiguous ----
    float* vplane = g_v + ((size_t)(img * 8 + g) * 16384 + px0) * 32;
    #pragma unroll
    for (int i = 0; i < 8; i++) {
        int idx = t + i * 256;          // 2048 float4 items
        int p = idx >> 3, q = idx & 7;
        float4 v4 = *(const float4*)(s_px + p * 36 + q * 4);
        *(float4*)(vplane + p * 32 + q * 4) = v4;
    }
}

// ============================ Kernel M ============================
// grid (8, 8, 16): z = img*8 + g. block 256 (one thread per center pixel).
__global__ __launch_bounds__(256, 4)
void combine_kernel(float* __restrict__ out)
{
    __shared__ __align__(16) float s_v[324 * 36];   // [hp][co] pitch 36

    const int t   = threadIdx.x;
    const int ty  = t >> 4, tx = t & 15;
    const int w0  = blockIdx.x * 16;
    const int h0  = blockIdx.y * 16;
    const int img = blockIdx.z >> 3;
    const int g   = blockIdx.z & 7;
    const int h   = h0 + ty, w = w0 + tx;
    const int px  = h * 128 + w;

    // ---- v halo gather first (overlap L2 latency with scalar work) ----
    const float* vt = g_v + (size_t)(img * 8 + g) * (16384u * 32u);
    #pragma unroll
    for (int i = 0; i < 11; i++) {
        int idx = t + i * 256;
        if (idx < 2592) {
            int hp = idx >> 3, q = idx & 7;
            int hy = hp / 18, hx = hp - hy * 18;
            int hh = h0 + hy - 1, ww = w0 + hx - 1;
            float4 v4 = make_float4(0.f, 0.f, 0.f, 0.f);
            if (((unsigned)hh < 128u) & ((unsigned)ww < 128u))
                v4 = *(const float4*)(vt + (size_t)(hh * 128 + ww) * 32 + q * 4);
            *(float4*)(s_v + hp * 36 + q * 4) = v4;
        }
    }

    // ---- logits: mask (9 strided coalesced) + neighbor (9 predicated) ----
    float a[9];
    {
        const float* nbg   = g_mn + ((size_t)img * 80 + g) * 16384;
        const float* mbase = g_mn + ((size_t)img * 80 + 8 + g * 9) * 16384 + px;
        #pragma unroll
        for (int k = 0; k < 9; k++) {
            int i = k / 3, j = k - i * 3;
            int hh = h + i - 1, ww = w + j - 1;
            float nb = 0.f;
            if (((unsigned)hh < 128u) & ((unsigned)ww < 128u))
                nb = nbg[hh * 128 + ww];
            a[k] = mbase[(size_t)k * 16384] + nb;
        }
        float mx = a[0];
        #pragma unroll
        for (int k = 1; k < 9; k++) mx = fmaxf(mx, a[k]);
        float s = 0.f;
        #pragma unroll
        for (int k = 0; k < 9; k++) { a[k] = __expf(a[k] - mx); s += a[k]; }
        float inv = 1.f / s;
        #pragma unroll
        for (int k = 0; k < 9; k++) a[k] *= inv;
    }
    __syncthreads();

    // ---- combine: out[c] = sum_k a[k] * v[c] at neighbor k ----
    {
        int hpk[9];
        #pragma unroll
        for (int k = 0; k < 9; k++) {
            int i = k / 3, j = k - i * 3;
            hpk[k] = ((ty + i) * 18 + (tx + j)) * 36;
        }
        float* ob = out + ((size_t)img * 256 + g * 32) * 16384 + px;
        #pragma unroll
        for (int c4 = 0; c4 < 8; c4++) {
            float ax = 0.f, ay = 0.f, az = 0.f, aw = 0.f;
            #pragma unroll
            for (int k = 0; k < 9; k++) {
                float4 vv = *(const float4*)(s_v + hpk[k] + c4 * 4);
                ax += a[k] * vv.x; ay += a[k] * vv.y;
                az += a[k] * vv.z; aw += a[k] * vv.w;
            }
            ob[(size_t)(c4 * 4 + 0) * 16384] = ax;
            ob[(size_t)(c4 * 4 + 1) * 16384] = ay;
            ob[(size_t)(c4 * 4 + 2) * 16384] = az;
            ob[(size_t)(c4 * 4 + 3) * 16384] = aw;
        }
    }
}

extern "C" void kernel_launch(void* const* d_in, const int* in_sizes, int n_in,
                              void* d_out, int out_size) {
    const float* x   = (const float*)d_in[0];
    const float* w1  = (const float*)d_in[1];
    const float* b1  = (const float*)d_in[2];
    const float* g1  = (const float*)d_in[3];
    const float* be1 = (const float*)d_in[4];
    const float* m1  = (const float*)d_in[5];
    const float* v1  = (const float*)d_in[6];
    const float* w2  = (const float*)d_in[7];
    const float* b2  = (const float*)d_in[8];
    const float* g2  = (const float*)d_in[9];
    const float* be2 = (const float*)d_in[10];
    const float* m2  = (const float*)d_in[11];
    const float* v2  = (const float*)d_in[12];
    const float* wv  = (const float*)d_in[13];
    float* out = (float*)d_out;

    stage1_kernel<<<dim3(64, 8, 2), 256>>>(x, w1, b1, g1, be1, m1, v1,
                                           w2, b2, g2, be2, m2, v2, wv);
    combine_kernel<<<dim3(8, 8, 16), 256>>>(out);
}

// round 5
// speedup vs baseline: 2.3865x; 1.0648x over previous
#include <cuda_runtime.h>

// LocalAttn, 2-kernel pipeline for GB300 (sm_103a), round 5.
// Kernel A (stage1): coalesced LDG.64 x staging into quad-swizzled smem rows,
//   x row -> registers, mn = bn2(conv2(tanh(bn1(conv1 x)))) -> g_mn,
//   v = wv @ x -> own smem row (swizzled) -> coalesced STG -> g_v.
// Kernel M (combine): gather v halo, softmax(mask+nb) in regs, combine.

typedef unsigned long long ull;

__device__ float g_v [2u * 8u * 16384u * 32u];   // [img][g][px][32]  33.5 MB
__device__ float g_mn[2u * 80u * 16384u];        // [img][ch][px]     10.5 MB

__device__ __forceinline__ ull fma2(ull a, ull b, ull c) {
    ull d;
    asm("fma.rn.f32x2 %0, %1, %2, %3;" : "=l"(d) : "l"(a), "l"(b), "l"(c));
    return d;
}
__device__ __forceinline__ float hadd2(ull a) {
    float x, y;
    asm("mov.b64 {%0,%1}, %2;" : "=f"(x), "=f"(y) : "l"(a));
    return x + y;
}

// ============================ Kernel A ============================
// grid (64, 8, 2) = (px chunk, group, img), block 256, one thread per pixel.
// smem x layout: word = px*36 + ((q ^ ((px>>3)&7))<<2) + w   (c = 4q + w)
__global__ __launch_bounds__(256, 3)
void stage1_kernel(
    const float* __restrict__ x,
    const float* __restrict__ w1, const float* __restrict__ b1,
    const float* __restrict__ g1, const float* __restrict__ be1,
    const float* __restrict__ m1, const float* __restrict__ v1,
    const float* __restrict__ w2, const float* __restrict__ b2,
    const float* __restrict__ g2, const float* __restrict__ be2,
    const float* __restrict__ m2, const float* __restrict__ v2,
    const float* __restrict__ wv)
{
    __shared__ __align__(16) float s_px[256 * 36];   // swizzled [px][ci]; later v
    __shared__ __align__(16) float s_w1g[256];       // w1[g]  (8,32)
    __shared__ __align__(16) float s_wvg[1024];      // wv[g]  (32,32)
    __shared__ __align__(16) float s_w2g[80];        // w2[g]  (10,8)
    __shared__ float s_a1[8], s_c1[8], s_a2[10], s_c2[10];

    const int t    = threadIdx.x;
    const int lane = t & 31;
    const int wq   = t >> 5;
    const int px0  = blockIdx.x * 256;
    const int g    = blockIdx.y;
    const int img  = blockIdx.z;

    // weights + folded BN params
    s_w1g[t] = w1[g * 256 + t];
    for (int i = t; i < 1024; i += 256) s_wvg[i] = wv[g * 1024 + i];
    if (t < 80) s_w2g[t] = w2[g * 80 + t];
    if (t < 8) {
        int ch = g * 8 + t;
        float inv = g1[ch] * rsqrtf(v1[ch] + 1e-5f);
        s_a1[t] = inv;
        s_c1[t] = b1[ch] * inv + be1[ch] - m1[ch] * inv;
    } else if (t >= 32 && t < 42) {
        int o = t - 32, ch = g * 10 + o;
        float inv = g2[ch] * rsqrtf(v2[ch] + 1e-5f);
        s_a2[o] = inv;
        s_c2[o] = b2[ch] * inv + be2[ch] - m2[ch] * inv;
    }

    // ---- coalesced x staging: warp wq handles channels [wq*4, wq*4+4) ----
    {
        const float* xg = x + ((size_t)img * 256 + g * 32) * 16384 + px0;
        #pragma unroll
        for (int it = 0; it < 4; ++it) {
            int c = wq * 4 + it;
            int q = c >> 2, wrd = c & 3;
            const float* src = xg + (size_t)c * 16384;
            #pragma unroll
            for (int seg = 0; seg < 4; ++seg) {
                int p = (lane + seg * 32) * 2;           // even pixel
                float2 v2 = *(const float2*)(src + p);
                int qs = ((q ^ ((p >> 3) & 7)) << 2) + wrd;
                s_px[p * 36 + qs]       = v2.x;
                s_px[(p + 1) * 36 + qs] = v2.y;
            }
        }
    }
    __syncthreads();

    // pull own x row into registers (logical quad order, physical swizzled)
    const int sw = (t >> 3) & 7;
    float* xrow = s_px + t * 36;
    ulonglong2 xr[8];
    #pragma unroll
    for (int q = 0; q < 8; q++)
        xr[q] = *(const ulonglong2*)(xrow + ((q ^ sw) << 2));

    // ---- conv1 -> bn -> tanh -> conv2 -> bn -> g_mn ----
    {
        ull acc[8];
        #pragma unroll
        for (int o = 0; o < 8; o++) acc[o] = 0ULL;
        #pragma unroll
        for (int q = 0; q < 8; q++) {
            #pragma unroll
            for (int o = 0; o < 8; o++) {
                ulonglong2 wp = *(const ulonglong2*)(s_w1g + o * 32 + q * 4);
                acc[o] = fma2(xr[q].x, wp.x, acc[o]);
                acc[o] = fma2(xr[q].y, wp.y, acc[o]);
            }
        }
        float tv[8];
        #pragma unroll
        for (int o = 0; o < 8; o++)
            tv[o] = tanhf(hadd2(acc[o]) * s_a1[o] + s_c1[o]);

        float* mb = g_mn + ((size_t)img * 80 + g * 10) * 16384 + px0 + t;
        #pragma unroll
        for (int o2 = 0; o2 < 10; o2++) {
            float a = 0.f;
            #pragma unroll
            for (int o = 0; o < 8; o++) a += tv[o] * s_w2g[o2 * 8 + o];
            mb[(size_t)o2 * 16384] = a * s_a2[o2] + s_c2[o2];
        }
    }

    // ---- v = wv @ x in 4 chunks of 8 outputs; write into own swizzled row ----
    #pragma unroll
    for (int ch = 0; ch < 4; ch++) {
        ull acc[8];
        #pragma unroll
        for (int o = 0; o < 8; o++) acc[o] = 0ULL;
        #pragma unroll
        for (int q = 0; q < 8; q++) {
            #pragma unroll
            for (int o = 0; o < 8; o++) {
                ulonglong2 wp = *(const ulonglong2*)(s_wvg + (ch * 8 + o) * 32 + q * 4);
                acc[o] = fma2(xr[q].x, wp.x, acc[o]);
                acc[o] = fma2(xr[q].y, wp.y, acc[o]);
            }
        }
        float4 r;
        r.x = hadd2(acc[0]); r.y = hadd2(acc[1]);
        r.z = hadd2(acc[2]); r.w = hadd2(acc[3]);
        *(float4*)(xrow + (((2 * ch)     ^ sw) << 2)) = r;
        r.x = hadd2(acc[4]); r.y = hadd2(acc[5]);
        r.z = hadd2(acc[6]); r.w = hadd2(acc[7]);
        *(float4*)(xrow + (((2 * ch + 1) ^ sw) << 2)) = r;
    }
    __syncthreads();

    // ---- coalesced store of v: warp writes 512B contiguous ----
    float* vplane = g_v + ((size_t)(img * 8 + g) * 16384 + px0) * 32;
    #pragma unroll
    for (int i = 0; i < 8; i++) {
        int idx = t + i * 256;          // 2048 float4 items
        int p = idx >> 3, q = idx & 7;
        int sp = (p >> 3) & 7;
        float4 v4 = *(const float4*)(s_px + p * 36 + ((q ^ sp) << 2));
        *(float4*)(vplane + p * 32 + q * 4) = v4;
    }
}

// ============================ Kernel M ============================
// grid (8, 8, 16): z = img*8 + g. block 256 (one thread per center pixel).
__global__ __launch_bounds__(256, 4)
void combine_kernel(float* __restrict__ out)
{
    __shared__ __align__(16) float s_v[324 * 36];   // [hp][co] pitch 36

    const int t   = threadIdx.x;
    const int ty  = t >> 4, tx = t & 15;
    const int w0  = blockIdx.x * 16;
    const int h0  = blockIdx.y * 16;
    const int img = blockIdx.z >> 3;
    const int g   = blockIdx.z & 7;
    const int h   = h0 + ty, w = w0 + tx;
    const int px  = h * 128 + w;

    // ---- v halo gather first (overlap L2 latency with scalar work) ----
    const float* vt = g_v + (size_t)(img * 8 + g) * (16384u * 32u);
    #pragma unroll
    for (int i = 0; i < 11; i++) {
        int idx = t + i * 256;
        if (idx < 2592) {
            int hp = idx >> 3, q = idx & 7;
            int hy = hp / 18, hx = hp - hy * 18;
            int hh = h0 + hy - 1, ww = w0 + hx - 1;
            float4 v4 = make_float4(0.f, 0.f, 0.f, 0.f);
            if (((unsigned)hh < 128u) & ((unsigned)ww < 128u))
                v4 = *(const float4*)(vt + (size_t)(hh * 128 + ww) * 32 + q * 4);
            *(float4*)(s_v + hp * 36 + q * 4) = v4;
        }
    }

    // ---- logits: mask (9 strided coalesced) + neighbor (9 predicated) ----
    float a[9];
    {
        const float* nbg   = g_mn + ((size_t)img * 80 + g) * 16384;
        const float* mbase = g_mn + ((size_t)img * 80 + 8 + g * 9) * 16384 + px;
        #pragma unroll
        for (int k = 0; k < 9; k++) {
            int i = k / 3, j = k - i * 3;
            int hh = h + i - 1, ww = w + j - 1;
            float nb = 0.f;
            if (((unsigned)hh < 128u) & ((unsigned)ww < 128u))
                nb = nbg[hh * 128 + ww];
            a[k] = mbase[(size_t)k * 16384] + nb;
        }
        float mx = a[0];
        #pragma unroll
        for (int k = 1; k < 9; k++) mx = fmaxf(mx, a[k]);
        float s = 0.f;
        #pragma unroll
        for (int k = 0; k < 9; k++) { a[k] = __expf(a[k] - mx); s += a[k]; }
        float inv = 1.f / s;
        #pragma unroll
        for (int k = 0; k < 9; k++) a[k] *= inv;
    }
    __syncthreads();

    // ---- combine: out[c] = sum_k a[k] * v[c] at neighbor k ----
    {
        int hpk[9];
        #pragma unroll
        for (int k = 0; k < 9; k++) {
            int i = k / 3, j = k - i * 3;
            hpk[k] = ((ty + i) * 18 + (tx + j)) * 36;
        }
        float* ob = out + ((size_t)img * 256 + g * 32) * 16384 + px;
        #pragma unroll
        for (int c4 = 0; c4 < 8; c4++) {
            float ax = 0.f, ay = 0.f, az = 0.f, aw = 0.f;
            #pragma unroll
            for (int k = 0; k < 9; k++) {
                float4 vv = *(const float4*)(s_v + hpk[k] + c4 * 4);
                ax += a[k] * vv.x; ay += a[k] * vv.y;
                az += a[k] * vv.z; aw += a[k] * vv.w;
            }
            ob[(size_t)(c4 * 4 + 0) * 16384] = ax;
            ob[(size_t)(c4 * 4 + 1) * 16384] = ay;
            ob[(size_t)(c4 * 4 + 2) * 16384] = az;
            ob[(size_t)(c4 * 4 + 3) * 16384] = aw;
        }
    }
}

extern "C" void kernel_launch(void* const* d_in, const int* in_sizes, int n_in,
                              void* d_out, int out_size) {
    const float* x   = (const float*)d_in[0];
    const float* w1  = (const float*)d_in[1];
    const float* b1  = (const float*)d_in[2];
    const float* g1  = (const float*)d_in[3];
    const float* be1 = (const float*)d_in[4];
    const float* m1  = (const float*)d_in[5];
    const float* v1  = (const float*)d_in[6];
    const float* w2  = (const float*)d_in[7];
    const float* b2  = (const float*)d_in[8];
    const float* g2  = (const float*)d_in[9];
    const float* be2 = (const float*)d_in[10];
    const float* m2  = (const float*)d_in[11];
    const float* v2  = (const float*)d_in[12];
    const float* wv  = (const float*)d_in[13];
    float* out = (float*)d_out;

    stage1_kernel<<<dim3(64, 8, 2), 256>>>(x, w1, b1, g1, be1, m1, v1,
                                           w2, b2, g2, be2, m2, v2, wv);
    combine_kernel<<<dim3(8, 8, 16), 256>>>(out);
}